// round 13
// baseline (speedup 1.0000x reference)
#include <cuda_runtime.h>
#include <cuda_bf16.h>

// CumAvgPool1d: y[..., t] = cumsum(x)[..., t] / (t+1)
// x: (8, 512, 16384) fp32 -> 4096 rows of T=16384.
//
// R12: identical structure to R11 (CTA-per-row, 8 warps, 256-elem chunks,
// depth-2 ring, HW-barrier total relay + width-8 shuffle combine), but
// __launch_bounds__(256, 5) caps regs at 51 to cross the occupancy cliff:
// 4 CTAs/SM (32 warps, 48%) -> 5 CTAs/SM (40 warps, 62%). More resident
// warps cover the per-round barrier/combine gaps in each CTA's request
// stream, pushing DRAM busy above 80%.

constexpr int T_LEN  = 16384;
constexpr int T_F4   = T_LEN / 4;          // 4096 float4 per row
constexpr int CHUNK_F4 = 64;               // 256 elems per chunk
constexpr int CHUNKS = T_F4 / CHUNK_F4;    // 64
constexpr int WARPS  = 8;
constexpr int THREADS = WARPS * 32;        // 256
constexpr int ROUNDS = CHUNKS / WARPS;     // 8

__global__ void __launch_bounds__(THREADS, 5)
cumavg_kernel(const float4* __restrict__ x, float4* __restrict__ y)
{
    __shared__ float relay[CHUNKS];

    const int tid  = threadIdx.x;
    const int lane = tid & 31;
    const int warp = tid >> 5;
    const int row  = blockIdx.x;

    const float4* px = x + (size_t)row * T_F4;
    float4*       py = y + (size_t)row * T_F4;

    // depth-2 prefetch ring over this warp's chunks (w, w+8, w+16, ...)
    float4 ra4[2], rb4[2];
    {
        const int c0 = warp;
        const int c1 = warp + WARPS;
        ra4[0] = __ldcs(px + c0 * CHUNK_F4 + lane);
        rb4[0] = __ldcs(px + c0 * CHUNK_F4 + 32 + lane);
        ra4[1] = __ldcs(px + c1 * CHUNK_F4 + lane);
        rb4[1] = __ldcs(px + c1 * CHUNK_F4 + 32 + lane);
    }

    float carry = 0.0f;
    // divisor base (exact integer floats): chunk c => t0 = c*256 + lane*4
    float tb = (float)(warp * 256 + lane * 4);

    #pragma unroll 2
    for (int k = 0; k < ROUNDS; ++k) {
        const int c = warp + WARPS * k;

        float4 a = ra4[k & 1];
        float4 b = rb4[k & 1];
        if (k + 2 < ROUNDS) {
            const int cn = c + 2 * WARPS;
            ra4[k & 1] = __ldcs(px + cn * CHUNK_F4 + lane);
            rb4[k & 1] = __ldcs(px + cn * CHUNK_F4 + 32 + lane);
        }

        // two independent local scans (4 elems each)
        float rA = a.x;  a.x = rA;
        rA += a.y;       a.y = rA;
        rA += a.z;       a.z = rA;
        rA += a.w;       a.w = rA;

        float rB = b.x;  b.x = rB;
        rB += b.y;       b.y = rB;
        rB += b.z;       b.z = rB;
        rB += b.w;       b.w = rB;

        // two interleaved warp scans (ILP 2)
        float wA = rA, wB = rB;
        #pragma unroll
        for (int d = 1; d < 32; d <<= 1) {
            float nA = __shfl_up_sync(0xffffffffu, wA, d);
            float nB = __shfl_up_sync(0xffffffffu, wB, d);
            if (lane >= d) { wA += nA; wB += nB; }
        }

        const float totalA = __shfl_sync(0xffffffffu, wA, 31);
        const float totalB = __shfl_sync(0xffffffffu, wB, 31);

        // publish chunk total; HW barrier publishes across warps
        if (lane == 0) relay[c] = totalA + totalB;
        __syncthreads();

        // combine the round's 8 totals: width-8 inclusive shuffle scan
        float s = relay[WARPS * k + (lane & (WARPS - 1))];
        #pragma unroll
        for (int d = 1; d < WARPS; d <<= 1) {
            float n = __shfl_up_sync(0xffffffffu, s, d, WARPS);
            if ((lane & (WARPS - 1)) >= d) s += n;
        }
        const float all = __shfl_sync(0xffffffffu, s, WARPS - 1, WARPS);
        const float pw  = __shfl_sync(0xffffffffu, s, (warp == 0 ? 0 : warp - 1), WARPS);
        const float P   = carry + (warp ? pw : 0.0f);
        carry += all;

        const float offA = P + (wA - rA);            // exclusive prefix, A half
        const float offB = P + totalA + (wB - rB);   // exclusive prefix, B half

        // y[t] = (off + local) / (t+1); divisors via float adds (exact ints)
        float4 o;
        o.x = (offA + a.x) * __fdividef(1.0f, tb + 1.0f);
        o.y = (offA + a.y) * __fdividef(1.0f, tb + 2.0f);
        o.z = (offA + a.z) * __fdividef(1.0f, tb + 3.0f);
        o.w = (offA + a.w) * __fdividef(1.0f, tb + 4.0f);
        __stcs(py + c * CHUNK_F4 + lane, o);

        o.x = (offB + b.x) * __fdividef(1.0f, tb + 129.0f);
        o.y = (offB + b.y) * __fdividef(1.0f, tb + 130.0f);
        o.z = (offB + b.z) * __fdividef(1.0f, tb + 131.0f);
        o.w = (offB + b.w) * __fdividef(1.0f, tb + 132.0f);
        __stcs(py + c * CHUNK_F4 + 32 + lane, o);

        tb += (float)(WARPS * 256);   // next owned chunk is 2048 elems ahead
    }
}

extern "C" void kernel_launch(void* const* d_in, const int* in_sizes, int n_in,
                              void* d_out, int out_size)
{
    const float* x = (const float*)d_in[0];
    float*       y = (float*)d_out;
    const int total = in_sizes[0];
    const int rows  = total / T_LEN;   // 4096 for the reference shape

    cumavg_kernel<<<rows, THREADS>>>((const float4*)x, (float4*)y);
}